// round 8
// baseline (speedup 1.0000x reference)
#include <cuda_runtime.h>

// MovingNCA, plane-reduced formulation:
//  state(96ch) -> 9 planes P_ij = <state, comms_w[i,j,:]>.
//  comms a = b_c + sum_ij P_ij(n+i,m+j); percep b = 3x3 img gather at perc pos.
//  s_c = sigmoid(a*u_c + b*v_c + ob_c); planes += W^T s; class ch -> scratch.
// R8: 2 cells/thread (best LDS amortization, R5) in a clean single wave
//     (128-thr blocks, 1024 blocks, launch_bounds(128,8) = 64 regs), and
//     hidden channels via tanh.approx with folded affine:
//       sigma(z) = 0.5 + 0.5 tanh(z/2);  w*s = (0.5w)*t + 0.5w
//     acc[q] initialized to K_q = sum_c 0.5 w_qc. Class+action channels keep
//     the ex2+rcp path (exact outputs, bit-stable perc decisions).

#define N_NEO 510
#define G     512
#define G2    (G * G)
#define NCELLS (N_NEO * N_NEO)
#define NCA_THRESH 0.0007f
#define NLOG2E (-1.4426950408889634f)

__device__ float   g_h[2][9][G2];       // ping-pong comms planes
__device__ float   g_cls[32][NCELLS];   // transposed class accumulators
__device__ ushort2 g_perc[NCELLS];      // perception positions

__global__ void nca_init() {
    long stride = (long)gridDim.x * blockDim.x;
    long tid = (long)blockIdx.x * blockDim.x + threadIdx.x;
    float* h = &g_h[0][0][0];
    for (long i = tid; i < 2L * 9 * G2; i += stride) h[i] = 0.0f;
    float* c = &g_cls[0][0];
    for (long i = tid; i < 32L * NCELLS; i += stride) c[i] = 0.0f;
    for (long i = tid; i < NCELLS; i += stride)
        g_perc[i] = make_ushort2((unsigned short)(i / N_NEO),
                                 (unsigned short)(i % N_NEO));
}

__global__ void nca_final(float* __restrict__ out) {
    int cell = blockIdx.x * 256 + threadIdx.x;
    if (cell >= NCELLS) return;
    float* op = out + (size_t)cell * 32;
#pragma unroll
    for (int k = 0; k < 32; k += 4) {
        float4 v;
        v.x = g_cls[k + 0][cell];
        v.y = g_cls[k + 1][cell];
        v.z = g_cls[k + 2][cell];
        v.w = g_cls[k + 3][cell];
        *reinterpret_cast<float4*>(op + k) = v;
    }
}

// exact-ish sigmoid; weights prescaled by -log2(e): x = -log2(e)*z
__device__ __forceinline__ float sigmoid_pre(float x) {
    float e;
    asm("ex2.approx.f32 %0, %1;" : "=f"(e) : "f"(x));
    float r;
    asm("rcp.approx.f32 %0, %1;" : "=f"(r) : "f"(1.0f + e));
    return r;
}

__device__ __forceinline__ float tanh_apx(float x) {
    float r;
    asm("tanh.approx.f32 %0, %1;" : "=f"(r) : "f"(x));
    return r;
}

__global__ __launch_bounds__(128, 8) void nca_step(
    const float* __restrict__ img,
    const float* __restrict__ comms_w,
    const float* __restrict__ comms_b,
    const float* __restrict__ perc_w,
    const float* __restrict__ perc_b,
    const float* __restrict__ out_w,
    const float* __restrict__ out_b,
    int parity)
{
    __shared__ __align__(16) float scwh[9 * 64];  // 0.5*comms_w, hidden ch
    __shared__ __align__(16) float scwc[9 * 32];  // comms_w, class ch
    __shared__ __align__(16) float su[100], sv[100], sob[100];  // prescaled
    __shared__ float spw[9], sK[9];
    __shared__ float sbias[2];                    // [0]=perc_b [1]=comms_b

    int t = threadIdx.y * 32 + threadIdx.x;
    for (int i = t; i < 864; i += 128) {
        int q = i / 96, c = i % 96;
        float w = comms_w[i];
        if (c < 64) scwh[q * 64 + c] = 0.5f * w;
        else        scwc[q * 32 + (c - 64)] = w;
    }
    if (t < 98) {
        float sc = (t < 64) ? 0.5f : NLOG2E;   // tanh half-arg vs ex2 prescale
        su[t]  = sc * out_w[t];
        sv[t]  = sc * out_w[98 + t];
        sob[t] = sc * out_b[t];
    }
    else if (t < 107) spw[t - 98] = perc_w[t - 98];
    else if (t == 107) sbias[0] = perc_b[0];
    else if (t == 108) sbias[1] = comms_b[0];
    __syncthreads();
    if (t < 9) {
        float k = 0.0f;
        for (int c = 0; c < 64; c++) k += scwh[t * 64 + c];
        sK[t] = k;                              // K_q = sum_c 0.5*w_qc
    }
    __syncthreads();

    int n = blockIdx.y * 4 + threadIdx.y;
    if (n >= N_NEO) return;
    int m0 = blockIdx.x * 64 + threadIdx.x;

    const float* __restrict__ hOld = &g_h[parity][0][0];
    float* __restrict__ hNew = &g_h[parity ^ 1][0][0];

    bool valid[2];
    int  cellc[2];
    float a[2], b[2];
    ushort2 pp[2];

#pragma unroll
    for (int u = 0; u < 2; u++) {
        int mm = m0 + 32 * u;
        valid[u] = (mm < N_NEO);
        int mc = mm < N_NEO ? mm : (N_NEO - 1);
        cellc[u] = n * N_NEO + mc;

        float av = sbias[1];
#pragma unroll
        for (int q = 0; q < 9; q++) {
            int i = q / 3, j = q % 3;
            av += hOld[q * G2 + (n + i) * G + (mc + j)];
        }
        a[u] = av;

        ushort2 p = g_perc[cellc[u]];
        pp[u] = p;
        float bv = sbias[0];
#pragma unroll
        for (int q = 0; q < 9; q++) {
            int i = q / 3, j = q % 3;
            bv = fmaf(img[(p.x + i) * G + (p.y + j)], spw[q], bv);
        }
        b[u] = bv;
    }

    float acc[2][9];
#pragma unroll
    for (int u = 0; u < 2; u++)
#pragma unroll
        for (int q = 0; q < 9; q++) acc[u][q] = sK[q];

    // ---- hidden channels 0..63 : tanh path, folded affine ----
#pragma unroll 4
    for (int c4 = 0; c4 < 64; c4 += 4) {
        float4 u4 = *reinterpret_cast<const float4*>(&su[c4]);
        float4 v4 = *reinterpret_cast<const float4*>(&sv[c4]);
        float4 o4 = *reinterpret_cast<const float4*>(&sob[c4]);
        float tt[2][4];
#pragma unroll
        for (int u = 0; u < 2; u++) {
            tt[u][0] = tanh_apx(fmaf(a[u], u4.x, fmaf(b[u], v4.x, o4.x)));
            tt[u][1] = tanh_apx(fmaf(a[u], u4.y, fmaf(b[u], v4.y, o4.y)));
            tt[u][2] = tanh_apx(fmaf(a[u], u4.z, fmaf(b[u], v4.z, o4.z)));
            tt[u][3] = tanh_apx(fmaf(a[u], u4.w, fmaf(b[u], v4.w, o4.w)));
        }
#pragma unroll
        for (int q = 0; q < 9; q++) {
            float4 w4 = *reinterpret_cast<const float4*>(&scwh[q * 64 + c4]);
#pragma unroll
            for (int u = 0; u < 2; u++)
                acc[u][q] = fmaf(w4.x, tt[u][0], fmaf(w4.y, tt[u][1],
                            fmaf(w4.z, tt[u][2], fmaf(w4.w, tt[u][3], acc[u][q]))));
        }
    }

    // ---- class channels 64..95 : exact path, RMW into scratch ----
#pragma unroll 2
    for (int k4 = 0; k4 < 32; k4 += 4) {
        float4 u4 = *reinterpret_cast<const float4*>(&su[64 + k4]);
        float4 v4 = *reinterpret_cast<const float4*>(&sv[64 + k4]);
        float4 o4 = *reinterpret_cast<const float4*>(&sob[64 + k4]);
        float s[2][4];
#pragma unroll
        for (int u = 0; u < 2; u++) {
            s[u][0] = sigmoid_pre(fmaf(a[u], u4.x, fmaf(b[u], v4.x, o4.x)));
            s[u][1] = sigmoid_pre(fmaf(a[u], u4.y, fmaf(b[u], v4.y, o4.y)));
            s[u][2] = sigmoid_pre(fmaf(a[u], u4.z, fmaf(b[u], v4.z, o4.z)));
            s[u][3] = sigmoid_pre(fmaf(a[u], u4.w, fmaf(b[u], v4.w, o4.w)));
        }
#pragma unroll
        for (int u = 0; u < 2; u++) {
            if (valid[u]) {
                int cc = cellc[u];
#pragma unroll
                for (int k = 0; k < 4; k++)
                    g_cls[k4 + k][cc] += s[u][k];   // coalesced across lanes
            }
        }
#pragma unroll
        for (int q = 0; q < 9; q++) {
            float4 w4 = *reinterpret_cast<const float4*>(&scwc[q * 32 + k4]);
#pragma unroll
            for (int u = 0; u < 2; u++)
                acc[u][q] = fmaf(w4.x, s[u][0], fmaf(w4.y, s[u][1],
                            fmaf(w4.z, s[u][2], fmaf(w4.w, s[u][3], acc[u][q]))));
        }
    }

    // ---- plane writes + action/perc update (exact path) ----
    float u96 = su[96], v96 = sv[96], o96 = sob[96];
    float u97 = su[97], v97 = sv[97], o97 = sob[97];
#pragma unroll
    for (int u = 0; u < 2; u++) {
        if (!valid[u]) continue;
        int mm = m0 + 32 * u;
        int hc = (n + 1) * G + (mm + 1);
#pragma unroll
        for (int q = 0; q < 9; q++)
            hNew[q * G2 + hc] = hOld[q * G2 + hc] + acc[u][q];

        float s0 = sigmoid_pre(fmaf(a[u], u96, fmaf(b[u], v96, o96)));
        float s1 = sigmoid_pre(fmaf(a[u], u97, fmaf(b[u], v97, o97)));
        int dx = (s0 > NCA_THRESH) ? 1 : ((s0 < -NCA_THRESH) ? -1 : 0);
        int dy = (s1 > NCA_THRESH) ? 1 : ((s1 < -NCA_THRESH) ? -1 : 0);
        int px = min(max((int)pp[u].x + dx, 0), N_NEO - 1);
        int py = min(max((int)pp[u].y + dy, 0), N_NEO - 1);
        g_perc[cellc[u]] = make_ushort2((unsigned short)px, (unsigned short)py);
    }
}

extern "C" void kernel_launch(void* const* d_in, const int* in_sizes, int n_in,
                              void* d_out, int out_size) {
    const float* img     = (const float*)d_in[0];
    const float* comms_w = (const float*)d_in[1];
    const float* comms_b = (const float*)d_in[2];
    const float* perc_w  = (const float*)d_in[3];
    const float* perc_b  = (const float*)d_in[4];
    const float* out_w   = (const float*)d_in[5];
    const float* out_b   = (const float*)d_in[6];
    float* out = (float*)d_out;

    nca_init<<<1024, 256>>>();

    dim3 bs(32, 4);
    dim3 gs((N_NEO + 63) / 64, (N_NEO + 3) / 4);   // 8 x 128 = 1024 blocks
    for (int t = 0; t < 50; t++)
        nca_step<<<gs, bs>>>(img, comms_w, comms_b, perc_w, perc_b,
                             out_w, out_b, t & 1);

    nca_final<<<(NCELLS + 255) / 256, 256>>>(out);
}

// round 9
// speedup vs baseline: 1.3621x; 1.3621x over previous
#include <cuda_runtime.h>

// MovingNCA, plane-reduced formulation:
//  state(96ch) -> 9 planes P_ij = <state, comms_w[i,j,:]>.
//  comms a = b_c + sum_ij P_ij(n+i,m+j); percep b = 3x3 img gather at perc pos.
//  s_c = sigmoid(a*u_c + b*v_c + ob_c); planes += W^T s; class ch -> scratch.
// R9: exact R5 shape (2 cells/thread, 256-thr blocks, 512 blocks, 64 regs)
//     with the class scratch vectorized: g_cls4[8][NCELLS] float4 ->
//     8 LDG.128 + 8 STG.128 per cell instead of 32+32 scalar (4x fewer
//     memory instructions, bit-identical adds).

#define N_NEO 510
#define G     512
#define G2    (G * G)
#define NCELLS (N_NEO * N_NEO)
#define NCA_THRESH 0.0007f
#define NLOG2E (-1.4426950408889634f)

__device__ float   g_h[2][9][G2];        // ping-pong comms planes
__device__ float4  g_cls4[8][NCELLS];    // class accumulators, 4 ch per float4
__device__ ushort2 g_perc[NCELLS];       // perception positions

__global__ void nca_init() {
    long stride = (long)gridDim.x * blockDim.x;
    long tid = (long)blockIdx.x * blockDim.x + threadIdx.x;
    float* h = &g_h[0][0][0];
    for (long i = tid; i < 2L * 9 * G2; i += stride) h[i] = 0.0f;
    float* c = &g_cls4[0][0].x;
    for (long i = tid; i < 32L * NCELLS; i += stride) c[i] = 0.0f;
    for (long i = tid; i < NCELLS; i += stride)
        g_perc[i] = make_ushort2((unsigned short)(i / N_NEO),
                                 (unsigned short)(i % N_NEO));
}

__global__ void nca_final(float* __restrict__ out) {
    int cell = blockIdx.x * 256 + threadIdx.x;
    if (cell >= NCELLS) return;
    float* op = out + (size_t)cell * 32;
#pragma unroll
    for (int j = 0; j < 8; j++)
        *reinterpret_cast<float4*>(op + 4 * j) = g_cls4[j][cell];
}

// weights prescaled by -log2(e): computes sigmoid(z) from x = -log2(e)*z
__device__ __forceinline__ float sigmoid_pre(float x) {
    float e;
    asm("ex2.approx.f32 %0, %1;" : "=f"(e) : "f"(x));
    float r;
    asm("rcp.approx.f32 %0, %1;" : "=f"(r) : "f"(1.0f + e));
    return r;
}

__global__ __launch_bounds__(256, 4) void nca_step(
    const float* __restrict__ img,
    const float* __restrict__ comms_w,
    const float* __restrict__ comms_b,
    const float* __restrict__ perc_w,
    const float* __restrict__ perc_b,
    const float* __restrict__ out_w,
    const float* __restrict__ out_b,
    int parity)
{
    __shared__ __align__(16) float scw[9 * 96];   // comms_w [ij][c]
    __shared__ __align__(16) float su[100], sv[100], sob[100];  // prescaled
    __shared__ float spw[9];
    __shared__ float sbias[2];                    // [0]=perc_b [1]=comms_b

    int t = threadIdx.y * 32 + threadIdx.x;
    for (int i = t; i < 864; i += 256) scw[i] = comms_w[i];
    if (t < 98) {
        su[t]  = NLOG2E * out_w[t];
        sv[t]  = NLOG2E * out_w[98 + t];
        sob[t] = NLOG2E * out_b[t];
    }
    else if (t < 107) spw[t - 98] = perc_w[t - 98];
    else if (t == 107) sbias[0] = perc_b[0];
    else if (t == 108) sbias[1] = comms_b[0];
    __syncthreads();

    int n = blockIdx.y * 8 + threadIdx.y;
    if (n >= N_NEO) return;
    int m0 = blockIdx.x * 64 + threadIdx.x;

    const float* __restrict__ hOld = &g_h[parity][0][0];
    float* __restrict__ hNew = &g_h[parity ^ 1][0][0];

    bool valid[2];
    int  cellc[2];            // clamped cell index (safe reads)
    float a[2], b[2];
    ushort2 pp[2];

#pragma unroll
    for (int u = 0; u < 2; u++) {
        int mm = m0 + 32 * u;
        valid[u] = (mm < N_NEO);
        int mc = mm < N_NEO ? mm : (N_NEO - 1);
        cellc[u] = n * N_NEO + mc;

        // comms gather over 9 planes
        float av = sbias[1];
#pragma unroll
        for (int q = 0; q < 9; q++) {
            int i = q / 3, j = q % 3;
            av += hOld[q * G2 + (n + i) * G + (mc + j)];
        }
        a[u] = av;

        // perception: 3x3 img patch at perc position
        ushort2 p = g_perc[cellc[u]];
        pp[u] = p;
        float bv = sbias[0];
#pragma unroll
        for (int q = 0; q < 9; q++) {
            int i = q / 3, j = q % 3;
            bv = fmaf(img[(p.x + i) * G + (p.y + j)], spw[q], bv);
        }
        b[u] = bv;
    }

    float acc[2][9];
#pragma unroll
    for (int u = 0; u < 2; u++)
#pragma unroll
        for (int q = 0; q < 9; q++) acc[u][q] = 0.0f;

    // ---- hidden channels 0..63 ----
#pragma unroll 4
    for (int c4 = 0; c4 < 64; c4 += 4) {
        float4 u4 = *reinterpret_cast<const float4*>(&su[c4]);
        float4 v4 = *reinterpret_cast<const float4*>(&sv[c4]);
        float4 o4 = *reinterpret_cast<const float4*>(&sob[c4]);
        float s[2][4];
#pragma unroll
        for (int u = 0; u < 2; u++) {
            s[u][0] = sigmoid_pre(fmaf(a[u], u4.x, fmaf(b[u], v4.x, o4.x)));
            s[u][1] = sigmoid_pre(fmaf(a[u], u4.y, fmaf(b[u], v4.y, o4.y)));
            s[u][2] = sigmoid_pre(fmaf(a[u], u4.z, fmaf(b[u], v4.z, o4.z)));
            s[u][3] = sigmoid_pre(fmaf(a[u], u4.w, fmaf(b[u], v4.w, o4.w)));
        }
#pragma unroll
        for (int q = 0; q < 9; q++) {
            float4 w4 = *reinterpret_cast<const float4*>(&scw[q * 96 + c4]);
#pragma unroll
            for (int u = 0; u < 2; u++)
                acc[u][q] = fmaf(w4.x, s[u][0], fmaf(w4.y, s[u][1],
                            fmaf(w4.z, s[u][2], fmaf(w4.w, s[u][3], acc[u][q]))));
        }
    }

    // ---- class channels 64..95 (vectorized RMW into float4 scratch) ----
#pragma unroll 2
    for (int c4 = 64; c4 < 96; c4 += 4) {
        float4 u4 = *reinterpret_cast<const float4*>(&su[c4]);
        float4 v4 = *reinterpret_cast<const float4*>(&sv[c4]);
        float4 o4 = *reinterpret_cast<const float4*>(&sob[c4]);
        float s[2][4];
#pragma unroll
        for (int u = 0; u < 2; u++) {
            s[u][0] = sigmoid_pre(fmaf(a[u], u4.x, fmaf(b[u], v4.x, o4.x)));
            s[u][1] = sigmoid_pre(fmaf(a[u], u4.y, fmaf(b[u], v4.y, o4.y)));
            s[u][2] = sigmoid_pre(fmaf(a[u], u4.z, fmaf(b[u], v4.z, o4.z)));
            s[u][3] = sigmoid_pre(fmaf(a[u], u4.w, fmaf(b[u], v4.w, o4.w)));
        }
        int j4 = (c4 - 64) >> 2;
#pragma unroll
        for (int u = 0; u < 2; u++) {
            if (valid[u]) {
                float4 v = g_cls4[j4][cellc[u]];
                v.x += s[u][0]; v.y += s[u][1]; v.z += s[u][2]; v.w += s[u][3];
                g_cls4[j4][cellc[u]] = v;
            }
        }
#pragma unroll
        for (int q = 0; q < 9; q++) {
            float4 w4 = *reinterpret_cast<const float4*>(&scw[q * 96 + c4]);
#pragma unroll
            for (int u = 0; u < 2; u++)
                acc[u][q] = fmaf(w4.x, s[u][0], fmaf(w4.y, s[u][1],
                            fmaf(w4.z, s[u][2], fmaf(w4.w, s[u][3], acc[u][q]))));
        }
    }

    // ---- plane writes + action/perc update ----
    float u96 = su[96], v96 = sv[96], o96 = sob[96];
    float u97 = su[97], v97 = sv[97], o97 = sob[97];
#pragma unroll
    for (int u = 0; u < 2; u++) {
        if (!valid[u]) continue;
        int mm = m0 + 32 * u;
        int hc = (n + 1) * G + (mm + 1);
#pragma unroll
        for (int q = 0; q < 9; q++)
            hNew[q * G2 + hc] = hOld[q * G2 + hc] + acc[u][q];

        float s0 = sigmoid_pre(fmaf(a[u], u96, fmaf(b[u], v96, o96)));
        float s1 = sigmoid_pre(fmaf(a[u], u97, fmaf(b[u], v97, o97)));
        int dx = (s0 > NCA_THRESH) ? 1 : ((s0 < -NCA_THRESH) ? -1 : 0);
        int dy = (s1 > NCA_THRESH) ? 1 : ((s1 < -NCA_THRESH) ? -1 : 0);
        int px = min(max((int)pp[u].x + dx, 0), N_NEO - 1);
        int py = min(max((int)pp[u].y + dy, 0), N_NEO - 1);
        g_perc[cellc[u]] = make_ushort2((unsigned short)px, (unsigned short)py);
    }
}

extern "C" void kernel_launch(void* const* d_in, const int* in_sizes, int n_in,
                              void* d_out, int out_size) {
    const float* img     = (const float*)d_in[0];
    const float* comms_w = (const float*)d_in[1];
    const float* comms_b = (const float*)d_in[2];
    const float* perc_w  = (const float*)d_in[3];
    const float* perc_b  = (const float*)d_in[4];
    const float* out_w   = (const float*)d_in[5];
    const float* out_b   = (const float*)d_in[6];
    float* out = (float*)d_out;

    nca_init<<<1024, 256>>>();

    dim3 bs(32, 8);
    dim3 gs((N_NEO + 63) / 64, (N_NEO + 7) / 8);   // 8 x 64 = 512 blocks
    for (int t = 0; t < 50; t++)
        nca_step<<<gs, bs>>>(img, comms_w, comms_b, perc_w, perc_b,
                             out_w, out_b, t & 1);

    nca_final<<<(NCELLS + 255) / 256, 256>>>(out);
}